// round 9
// baseline (speedup 1.0000x reference)
#include <cuda_runtime.h>
#include <cuda_bf16.h>
#include <cstdint>

#define BB 8
#define SS 4096
#define EE 768
#define JMAX 2048
#define INV_SQRT_DK 0.03608439182435161f

#define NX ((size_t)BB * SS * EE)     // 25.2M
#define NK ((size_t)BB * JMAX * EE)   // 12.6M
#define NP ((size_t)BB * SS * JMAX)   // 67.1M

// ---------------- scratch (device globals; no allocations allowed) ----------
__device__ __nv_bfloat16 g_Xhi[NX], g_Xlo[NX];
__device__ __nv_bfloat16 g_Wqh[EE * EE], g_Wql[EE * EE];
__device__ __nv_bfloat16 g_Wkh[EE * EE], g_Wkl[EE * EE];
__device__ __nv_bfloat16 g_Qhi[NX], g_Qlo[NX];
__device__ __nv_bfloat16 g_Khi[NK], g_Klo[NK];
__device__ __nv_bfloat16 g_Vth[NK], g_Vtl[NK];   // [b][e][token] transposed V splits
__device__ float g_P[NP];
__device__ __nv_bfloat16 g_Phi[NP], g_Plo[NP];   // unnormalized exp splits
__device__ float g_invl[BB * SS];                 // per-row 1/sum

// ---------------- helpers ----------------------------------------------------
__device__ __forceinline__ uint32_t smem_to_u32(const void* p) {
    uint32_t a;
    asm("{ .reg .u64 t; cvta.to.shared.u64 t, %1; cvt.u32.u64 %0, t; }" : "=r"(a) : "l"(p));
    return a;
}
__device__ __forceinline__ int seq_first(const int* __restrict__ s, int b) {
    const bool is64 = (s[1] == 0);
    int v = is64 ? s[4 * b] : s[2 * b];
    if (v < 1) v = 1;
    if (v > JMAX) v = JMAX;
    return v;
}
__device__ __forceinline__ void split2(float v, __nv_bfloat16& h, __nv_bfloat16& l) {
    h = __float2bfloat16(v);
    l = __float2bfloat16(v - __bfloat162float(h));
}
__device__ __forceinline__ uint32_t packbf(__nv_bfloat16 a, __nv_bfloat16 b) {
    return (uint32_t)__bfloat16_as_ushort(a) | ((uint32_t)__bfloat16_as_ushort(b) << 16);
}

__device__ __forceinline__ void ldsm4(uint32_t* d, uint32_t a) {
    asm volatile("ldmatrix.sync.aligned.m8n8.x4.shared.b16 {%0,%1,%2,%3}, [%4];"
                 : "=r"(d[0]), "=r"(d[1]), "=r"(d[2]), "=r"(d[3]) : "r"(a));
}
__device__ __forceinline__ void mma_bf16(float* c, const uint32_t* a, uint32_t b0, uint32_t b1) {
    asm volatile(
        "mma.sync.aligned.m16n8k16.row.col.f32.bf16.bf16.f32 "
        "{%0,%1,%2,%3}, {%4,%5,%6,%7}, {%8,%9}, {%0,%1,%2,%3};"
        : "+f"(c[0]), "+f"(c[1]), "+f"(c[2]), "+f"(c[3])
        : "r"(a[0]), "r"(a[1]), "r"(a[2]), "r"(a[3]), "r"(b0), "r"(b1));
}
#define CP_ASYNC16(sa, ga) \
    asm volatile("cp.async.cg.shared.global [%0], [%1], 16;" :: "r"(sa), "l"(ga) : "memory")
#define CP_COMMIT() asm volatile("cp.async.commit_group;" ::: "memory")
#define CP_WAIT(n)  asm volatile("cp.async.wait_group %0;" :: "n"(n) : "memory")

// ---------------- kernel: fp32 -> (hi, lo) bf16 splits ------------------------
__global__ __launch_bounds__(256) void split_sel(const float* __restrict__ src,
                                                 int sel, size_t n4)
{
    size_t i = (size_t)blockIdx.x * 256 + threadIdx.x;
    if (i >= n4) return;
    __nv_bfloat16 *dh, *dl;
    if (sel == 0)      { dh = g_Xhi; dl = g_Xlo; }
    else if (sel == 1) { dh = g_Wqh; dl = g_Wql; }
    else               { dh = g_Wkh; dl = g_Wkl; }
    float4 v = ((const float4*)src)[i];
    __nv_bfloat16 h0, l0, h1, l1, h2, l2, h3, l3;
    split2(v.x, h0, l0); split2(v.y, h1, l1);
    split2(v.z, h2, l2); split2(v.w, h3, l3);
    ((uint2*)dh)[i] = make_uint2(packbf(h0, h1), packbf(h2, h3));
    ((uint2*)dl)[i] = make_uint2(packbf(l0, l1), packbf(l2, l3));
}

// ---------------- generic split-bf16 NT GEMM on mma.sync ---------------------
// D[128x128] = (Ahi+Alo)[128xK] * (Bhi+Blo)[128xK]^T  (3 bf16 products, f32 acc)
// 128 threads (4 warps, 2x2 grid, 64x64 warp tile), 2 CTAs/SM.
#define TSTRIDE 80
#define TILE_SM (128 * TSTRIDE)          // 10240
#define STAGE_SM (4 * TILE_SM)           // 40960
#define SMEM_TC (2 * STAGE_SM)           // 81920

#define MODE_PROJQ 0
#define MODE_PROJK 1
#define MODE_SCORE 2
#define MODE_PV    3

__global__ __launch_bounds__(128, 2) void tc_gemm(int mode, const int* __restrict__ seq,
                                                  const float* __restrict__ bias,
                                                  float* __restrict__ Hout, int bsel)
{
    const int n0 = blockIdx.x << 7;
    int b = 0, first = 0, Kdim = EE;
    size_t arow, brow, orow;
    int lda, ldb, ldo = EE;
    const __nv_bfloat16 *Ah, *Al, *Bh, *Bl;
    float* outF = nullptr;
    __nv_bfloat16 *oHi = nullptr, *oLo = nullptr;
    float scale = 1.f;
    bool addb = false;

    if (mode == MODE_PROJQ) {
        arow = (size_t)blockIdx.y << 7; brow = n0; orow = arow;
        Ah = g_Xhi; Al = g_Xlo; lda = EE; Bh = g_Wqh; Bl = g_Wql; ldb = EE;
        oHi = g_Qhi; oLo = g_Qlo; ldo = EE; addb = true;
    } else if (mode == MODE_PROJK) {
        b = blockIdx.y >> 4;
        int tloc = (blockIdx.y & 15) << 7;
        first = seq_first(seq, b);
        if (tloc >= first) return;
        arow = (size_t)b * SS + tloc; brow = n0; orow = (size_t)b * JMAX + tloc;
        Ah = g_Xhi; Al = g_Xlo; lda = EE; Bh = g_Wkh; Bl = g_Wkl; ldb = EE;
        oHi = g_Khi; oLo = g_Klo; ldo = EE; addb = true;
    } else if (mode == MODE_SCORE) {
        b = bsel; first = seq_first(seq, b);
        if (n0 >= first) return;
        arow = (size_t)b * SS + ((size_t)blockIdx.y << 7);
        brow = (size_t)b * JMAX + n0;
        Ah = g_Qhi; Al = g_Qlo; lda = EE; Bh = g_Khi; Bl = g_Klo; ldb = EE;
        outF = g_P; ldo = JMAX; orow = arow; scale = INV_SQRT_DK;
    } else { // MODE_PV
        b = bsel; first = seq_first(seq, b);
        Kdim = (first + 63) & ~63;
        arow = (size_t)b * SS + ((size_t)blockIdx.y << 7);
        brow = (size_t)b * EE + n0;
        Ah = g_Phi; Al = g_Plo; lda = JMAX; Bh = g_Vth; Bl = g_Vtl; ldb = JMAX;
        outF = Hout; ldo = EE; orow = arow;
    }

    extern __shared__ char smem[];
    const uint32_t sbase = smem_to_u32(smem);
    const int tid  = threadIdx.x;
    const int lane = tid & 31, wid = tid >> 5;
    const int wm = wid >> 1, wn = wid & 1;          // 2 x 2 warp grid, warp tile 64x64

    const char* gsrc[4] = { (const char*)(Ah + arow * lda), (const char*)(Al + arow * lda),
                            (const char*)(Bh + brow * ldb), (const char*)(Bl + brow * ldb) };
    const size_t ldby[4] = { (size_t)lda * 2, (size_t)lda * 2,
                             (size_t)ldb * 2, (size_t)ldb * 2 };

    auto load_stage = [&](int s, int ki) {
        const size_t k0b = (size_t)ki * 64;          // 32 bf16 = 64 bytes
        const uint32_t sb = sbase + s * STAGE_SM;
        #pragma unroll
        for (int j = 0; j < 16; j++) {
            int t = tid + j * 128;                   // 2048 chunks of 16B
            int tile = t >> 9, row = (t >> 2) & 127, c = t & 3;
            uint32_t sa = sb + tile * TILE_SM + row * TSTRIDE + c * 16;
            const char* ga = gsrc[tile] + (size_t)row * ldby[tile] + k0b + c * 16;
            CP_ASYNC16(sa, ga);
        }
    };

    float acc[4][8][4];
    #pragma unroll
    for (int mt = 0; mt < 4; mt++)
        #pragma unroll
        for (int nt = 0; nt < 8; nt++)
            #pragma unroll
            for (int r = 0; r < 4; r++) acc[mt][nt][r] = 0.f;

    const int kt = Kdim >> 5;                        // BK = 32

    load_stage(0, 0);
    CP_COMMIT();

    for (int i = 0; i < kt; i++) {
        const int cur = i & 1;
        if (i + 1 < kt) { load_stage(cur ^ 1, i + 1); CP_COMMIT(); CP_WAIT(1); }
        else            { CP_WAIT(0); }
        __syncthreads();

        const uint32_t sb = sbase + cur * STAGE_SM;
        #pragma unroll
        for (int ks = 0; ks < 2; ks++) {             // two k16 halves of BK=32
            uint32_t ah[4][4], alr[4][4];
            #pragma unroll
            for (int mt = 0; mt < 4; mt++) {
                uint32_t ra = sb + (wm * 64 + mt * 16 + (lane & 15)) * TSTRIDE
                            + ks * 32 + ((lane >> 4) << 4);
                ldsm4(ah[mt],  ra);
                ldsm4(alr[mt], ra + TILE_SM);
            }
            uint32_t bh4[4][4], bl4[4][4];
            #pragma unroll
            for (int nt2 = 0; nt2 < 4; nt2++) {
                uint32_t rb = sb + 2 * TILE_SM
                            + (wn * 64 + nt2 * 16 + ((lane & 7) + ((lane >> 4) << 3))) * TSTRIDE
                            + ks * 32 + (((lane >> 3) & 1) << 4);
                ldsm4(bh4[nt2], rb);
                ldsm4(bl4[nt2], rb + TILE_SM);
            }
            #pragma unroll
            for (int p = 0; p < 3; p++) {
                #pragma unroll
                for (int mt = 0; mt < 4; mt++)
                    #pragma unroll
                    for (int nt2 = 0; nt2 < 4; nt2++)
                        #pragma unroll
                        for (int nn = 0; nn < 2; nn++) {
                            float* c = acc[mt][nt2 * 2 + nn];
                            const uint32_t* a = (p == 2) ? alr[mt] : ah[mt];
                            const uint32_t* bb = (p == 1) ? bl4[nt2] : bh4[nt2];
                            mma_bf16(c, a, bb[2 * nn], bb[2 * nn + 1]);
                        }
            }
        }
        __syncthreads();
    }

    // epilogue
    const int grp = lane >> 2, tig = lane & 3;
    #pragma unroll
    for (int mt = 0; mt < 4; mt++) {
        #pragma unroll
        for (int half = 0; half < 2; half++) {
            const size_t row = orow + wm * 64 + mt * 16 + grp + half * 8;
            float rsc = scale;
            if (mode == MODE_PV) rsc = g_invl[row];
            #pragma unroll
            for (int nt = 0; nt < 8; nt++) {
                const int col = n0 + wn * 64 + nt * 8 + tig * 2;
                float v0 = acc[mt][nt][half * 2 + 0];
                float v1 = acc[mt][nt][half * 2 + 1];
                if (outF) {
                    *(float2*)&outF[row * ldo + col] = make_float2(v0 * rsc, v1 * rsc);
                } else {
                    if (addb) { v0 += bias[col]; v1 += bias[col + 1]; }
                    __nv_bfloat16 h0, l0, h1, l1;
                    split2(v0, h0, l0); split2(v1, h1, l1);
                    *(uint32_t*)&oHi[row * ldo + col] = packbf(h0, h1);
                    *(uint32_t*)&oLo[row * ldo + col] = packbf(l0, l1);
                }
            }
        }
    }
}

// ---------------- kernel: V projection (SIMT fp32), transposed split output --
__global__ __launch_bounds__(256) void v_gemm(
    const float* __restrict__ X, const float* __restrict__ W,
    const float* __restrict__ bias, const int* __restrict__ seq)
{
    const int tid = threadIdx.x;
    const int tx = tid & 15;
    const int ty = tid >> 4;

    const int b    = blockIdx.y >> 4;
    const int tloc = (blockIdx.y & 15) << 7;
    const int col0 = blockIdx.x << 7;
    const int first = seq_first(seq, b);
    if (tloc >= first) return;

    const int xrow0 = b * SS + tloc;

    __shared__ float As[16][128];
    __shared__ float Bs[16][128];

    float acc[8][8];
    #pragma unroll
    for (int i = 0; i < 8; i++)
        #pragma unroll
        for (int j = 0; j < 8; j++) acc[i][j] = 0.f;

    for (int k0 = 0; k0 < EE; k0 += 16) {
        #pragma unroll
        for (int v = tid; v < 512; v += 256) {
            int r = v >> 2;
            int c = (v & 3) << 2;
            float4 a = *(const float4*)&X[(size_t)(xrow0 + r) * EE + k0 + c];
            As[c + 0][r] = a.x; As[c + 1][r] = a.y;
            As[c + 2][r] = a.z; As[c + 3][r] = a.w;
            float4 wv = *(const float4*)&W[(size_t)(col0 + r) * EE + k0 + c];
            Bs[c + 0][r] = wv.x; Bs[c + 1][r] = wv.y;
            Bs[c + 2][r] = wv.z; Bs[c + 3][r] = wv.w;
        }
        __syncthreads();

        #pragma unroll
        for (int kk = 0; kk < 16; kk++) {
            float4 a0 = *(const float4*)&As[kk][ty * 8];
            float4 a1 = *(const float4*)&As[kk][ty * 8 + 4];
            float4 b0 = *(const float4*)&Bs[kk][tx * 8];
            float4 b1 = *(const float4*)&Bs[kk][tx * 8 + 4];
            float av[8] = {a0.x, a0.y, a0.z, a0.w, a1.x, a1.y, a1.z, a1.w};
            float bv[8] = {b0.x, b0.y, b0.z, b0.w, b1.x, b1.y, b1.z, b1.w};
            #pragma unroll
            for (int i = 0; i < 8; i++)
                #pragma unroll
                for (int j = 0; j < 8; j++)
                    acc[i][j] = fmaf(av[i], bv[j], acc[i][j]);
        }
        __syncthreads();
    }

    const int tok0 = tloc + ty * 8;
    #pragma unroll
    for (int j = 0; j < 8; j++) {
        const int e = col0 + tx * 8 + j;
        const float be = bias[e];
        uint32_t hu[4], lu[4];
        #pragma unroll
        for (int pr = 0; pr < 4; pr++) {
            __nv_bfloat16 h0, l0, h1, l1;
            split2(acc[pr * 2 + 0][j] + be, h0, l0);
            split2(acc[pr * 2 + 1][j] + be, h1, l1);
            hu[pr] = packbf(h0, h1);
            lu[pr] = packbf(l0, l1);
        }
        const size_t off = ((size_t)b * EE + e) * JMAX + tok0;
        *(uint4*)&g_Vth[off] = make_uint4(hu[0], hu[1], hu[2], hu[3]);
        *(uint4*)&g_Vtl[off] = make_uint4(lu[0], lu[1], lu[2], lu[3]);
    }
}

// ---------------- kernel: masked softmax (2-pass, unnormalized exp out) ------
__global__ __launch_bounds__(256) void softmax_rows(const int* __restrict__ seq, int bsel)
{
    const int b = bsel;
    const int q = blockIdx.x;
    const int first = seq_first(seq, b);
    const float* row = g_P + ((size_t)b * SS + q) * JMAX;
    const int tid = threadIdx.x;

    __shared__ float red[256];

    float m = -1e30f;
    for (int j = 1 + tid; j < first; j += 256) m = fmaxf(m, row[j]);
    red[tid] = m;
    __syncthreads();
    #pragma unroll
    for (int s = 128; s > 0; s >>= 1) {
        if (tid < s) red[tid] = fmaxf(red[tid], red[tid + s]);
        __syncthreads();
    }
    m = red[0];
    __syncthreads();

    // pass 2: write unnormalized exp splits, accumulate l
    const int kpad = (first + 63) & ~63;
    const size_t ro = ((size_t)b * SS + q) * JMAX;
    float l = 0.f;
    for (int j = tid; j < kpad; j += 256) {
        float p = 0.f;
        if (j >= 1 && j < first) { p = __expf(row[j] - m); l += p; }
        __nv_bfloat16 h, lo;
        split2(p, h, lo);
        g_Phi[ro + j] = h;
        g_Plo[ro + j] = lo;
    }
    red[tid] = l;
    __syncthreads();
    #pragma unroll
    for (int s = 128; s > 0; s >>= 1) {
        if (tid < s) red[tid] += red[tid + s];
        __syncthreads();
    }
    if (tid == 0) g_invl[b * SS + q] = 1.0f / fmaxf(red[0], 1e-30f);
}

// ---------------------------------------------------------------------------
extern "C" void kernel_launch(void* const* d_in, const int* in_sizes, int n_in,
                              void* d_out, int out_size)
{
    const float* ebd = (const float*)d_in[0];
    const int*   seq = (const int*)d_in[1];
    const float* Wq = (const float*)d_in[2];
    const float* bq = (const float*)d_in[3];
    const float* Wk = (const float*)d_in[4];
    const float* bk = (const float*)d_in[5];
    const float* Wv = (const float*)d_in[6];
    const float* bv = (const float*)d_in[7];
    float* H = (float*)d_out;

    static cudaStream_t s2 = nullptr;
    static cudaEvent_t evFork = nullptr, evWsplit = nullptr, evXsplit = nullptr;
    static cudaEvent_t evK = nullptr, evQ = nullptr, evChain = nullptr;
    if (!s2) {
        cudaFuncSetAttribute(tc_gemm, cudaFuncAttributeMaxDynamicSharedMemorySize, SMEM_TC);
        cudaStreamCreateWithFlags(&s2, cudaStreamNonBlocking);
        cudaEventCreateWithFlags(&evFork, cudaEventDisableTiming);
        cudaEventCreateWithFlags(&evWsplit, cudaEventDisableTiming);
        cudaEventCreateWithFlags(&evXsplit, cudaEventDisableTiming);
        cudaEventCreateWithFlags(&evK, cudaEventDisableTiming);
        cudaEventCreateWithFlags(&evQ, cudaEventDisableTiming);
        cudaEventCreateWithFlags(&evChain, cudaEventDisableTiming);
    }

    const size_t w4 = (size_t)EE * EE / 4;
    const size_t n4 = NX / 4;

    // fork s2: v_gemm (no deps) + W-splits
    cudaEventRecord(evFork, 0);
    cudaStreamWaitEvent(s2, evFork, 0);
    v_gemm<<<dim3(EE / 128, BB * (JMAX / 128)), 256, 0, s2>>>(ebd, Wv, bv, seq);
    split_sel<<<(unsigned)((w4 + 255) / 256), 256, 0, s2>>>(Wq, 1, w4);
    split_sel<<<(unsigned)((w4 + 255) / 256), 256, 0, s2>>>(Wk, 2, w4);
    cudaEventRecord(evWsplit, s2);

    // main: X split
    split_sel<<<(unsigned)((n4 + 255) / 256), 256>>>(ebd, 0, n4);
    cudaEventRecord(evXsplit, 0);

    // PROJK on s2 (needs X split + Wk split); PROJQ on main (needs Wq split)
    cudaStreamWaitEvent(s2, evXsplit, 0);
    tc_gemm<<<dim3(EE / 128, BB * (JMAX / 128), 1), 128, SMEM_TC, s2>>>(MODE_PROJK, seq, bk, nullptr, -1);
    cudaEventRecord(evK, s2);

    cudaStreamWaitEvent(0, evWsplit, 0);
    tc_gemm<<<dim3(EE / 128, BB * SS / 128, 1), 128, SMEM_TC>>>(MODE_PROJQ, seq, bq, nullptr, -1);
    cudaEventRecord(evQ, 0);

    // cross-join: main needs K; s2 needs Q
    cudaStreamWaitEvent(0, evK, 0);
    cudaStreamWaitEvent(s2, evQ, 0);

    // per-batch pipelined chains: even batches on main, odd on s2
    for (int b = 0; b < BB; b++) {
        cudaStream_t st = (b & 1) ? s2 : (cudaStream_t)0;
        tc_gemm<<<dim3(JMAX / 128, SS / 128, 1), 128, SMEM_TC, st>>>(MODE_SCORE, seq, nullptr, nullptr, b);
        softmax_rows<<<SS, 256, 0, st>>>(seq, b);
        tc_gemm<<<dim3(EE / 128, SS / 128, 1), 128, SMEM_TC, st>>>(MODE_PV, seq, nullptr, H, b);
    }

    // join s2 back to main
    cudaEventRecord(evChain, s2);
    cudaStreamWaitEvent(0, evChain, 0);
}

// round 10
// speedup vs baseline: 1.0533x; 1.0533x over previous
#include <cuda_runtime.h>
#include <cuda_bf16.h>
#include <cstdint>

#define BB 8
#define SS 4096
#define EE 768
#define JMAX 2048
#define INV_SQRT_DK 0.03608439182435161f

#define NX ((size_t)BB * SS * EE)     // 25.2M
#define NK ((size_t)BB * JMAX * EE)   // 12.6M
#define NP ((size_t)BB * SS * JMAX)   // 67.1M

// ---------------- scratch (device globals; no allocations allowed) ----------
__device__ __nv_bfloat16 g_Xhi[NX], g_Xlo[NX];
__device__ __nv_bfloat16 g_Wqh[EE * EE], g_Wql[EE * EE];
__device__ __nv_bfloat16 g_Wkh[EE * EE], g_Wkl[EE * EE];
__device__ __nv_bfloat16 g_Qhi[NX], g_Qlo[NX];
__device__ __nv_bfloat16 g_Khi[NK], g_Klo[NK];
__device__ __nv_bfloat16 g_Vth[NK], g_Vtl[NK];   // [b][e][token] transposed V splits
__device__ float g_P[NP];
__device__ __nv_bfloat16 g_Phi[NP], g_Plo[NP];   // unnormalized exp splits
__device__ float g_invl[BB * SS];                 // per-row 1/sum
__device__ unsigned int g_rowmax[BB * SS];        // encoded per-row max (memset 0)

// ---------------- helpers ----------------------------------------------------
__device__ __forceinline__ uint32_t smem_to_u32(const void* p) {
    uint32_t a;
    asm("{ .reg .u64 t; cvta.to.shared.u64 t, %1; cvt.u32.u64 %0, t; }" : "=r"(a) : "l"(p));
    return a;
}
__device__ __forceinline__ int seq_first(const int* __restrict__ s, int b) {
    const bool is64 = (s[1] == 0);
    int v = is64 ? s[4 * b] : s[2 * b];
    if (v < 1) v = 1;
    if (v > JMAX) v = JMAX;
    return v;
}
__device__ __forceinline__ void split2(float v, __nv_bfloat16& h, __nv_bfloat16& l) {
    h = __float2bfloat16(v);
    l = __float2bfloat16(v - __bfloat162float(h));
}
__device__ __forceinline__ uint32_t packbf(__nv_bfloat16 a, __nv_bfloat16 b) {
    return (uint32_t)__bfloat16_as_ushort(a) | ((uint32_t)__bfloat16_as_ushort(b) << 16);
}
// order-preserving float<->uint encode (for atomicMax); 0 == "nothing yet"
__device__ __forceinline__ uint32_t fenc(float f) {
    int s = __float_as_int(f);
    return (uint32_t)(s ^ ((s >> 31) | 0x80000000));
}
__device__ __forceinline__ float fdec(uint32_t u) {
    int s = (u & 0x80000000u) ? (int)(u ^ 0x80000000u) : ~(int)u;
    return __int_as_float(s);
}

__device__ __forceinline__ void ldsm4(uint32_t* d, uint32_t a) {
    asm volatile("ldmatrix.sync.aligned.m8n8.x4.shared.b16 {%0,%1,%2,%3}, [%4];"
                 : "=r"(d[0]), "=r"(d[1]), "=r"(d[2]), "=r"(d[3]) : "r"(a));
}
__device__ __forceinline__ void mma_bf16(float* c, const uint32_t* a, uint32_t b0, uint32_t b1) {
    asm volatile(
        "mma.sync.aligned.m16n8k16.row.col.f32.bf16.bf16.f32 "
        "{%0,%1,%2,%3}, {%4,%5,%6,%7}, {%8,%9}, {%0,%1,%2,%3};"
        : "+f"(c[0]), "+f"(c[1]), "+f"(c[2]), "+f"(c[3])
        : "r"(a[0]), "r"(a[1]), "r"(a[2]), "r"(a[3]), "r"(b0), "r"(b1));
}
#define CP_ASYNC16(sa, ga) \
    asm volatile("cp.async.cg.shared.global [%0], [%1], 16;" :: "r"(sa), "l"(ga) : "memory")
#define CP_COMMIT() asm volatile("cp.async.commit_group;" ::: "memory")
#define CP_WAIT(n)  asm volatile("cp.async.wait_group %0;" :: "n"(n) : "memory")

// ---------------- kernel: fp32 -> (hi, lo) bf16 splits ------------------------
__global__ __launch_bounds__(256) void split_sel(const float* __restrict__ src,
                                                 int sel, size_t n4)
{
    size_t i = (size_t)blockIdx.x * 256 + threadIdx.x;
    if (i >= n4) return;
    __nv_bfloat16 *dh, *dl;
    if (sel == 0)      { dh = g_Xhi; dl = g_Xlo; }
    else if (sel == 1) { dh = g_Wqh; dl = g_Wql; }
    else               { dh = g_Wkh; dl = g_Wkl; }
    float4 v = ((const float4*)src)[i];
    __nv_bfloat16 h0, l0, h1, l1, h2, l2, h3, l3;
    split2(v.x, h0, l0); split2(v.y, h1, l1);
    split2(v.z, h2, l2); split2(v.w, h3, l3);
    ((uint2*)dh)[i] = make_uint2(packbf(h0, h1), packbf(h2, h3));
    ((uint2*)dl)[i] = make_uint2(packbf(l0, l1), packbf(l2, l3));
}

// ---------------- generic split-bf16 NT GEMM on mma.sync ---------------------
#define TSTRIDE 80
#define TILE_SM (128 * TSTRIDE)          // 10240
#define STAGE_SM (4 * TILE_SM)           // 40960
#define SMEM_TC (2 * STAGE_SM)           // 81920

#define MODE_PROJQ 0
#define MODE_PROJK 1
#define MODE_SCORE 2
#define MODE_PV    3

__global__ __launch_bounds__(128, 2) void tc_gemm(int mode, const int* __restrict__ seq,
                                                  const float* __restrict__ bias,
                                                  float* __restrict__ Hout)
{
    const int n0 = blockIdx.x << 7;
    int b = 0, first = 0, Kdim = EE;
    size_t arow, brow, orow;
    int lda, ldb, ldo = EE;
    const __nv_bfloat16 *Ah, *Al, *Bh, *Bl;
    float* outF = nullptr;
    __nv_bfloat16 *oHi = nullptr, *oLo = nullptr;
    float scale = 1.f;
    bool addb = false;

    if (mode == MODE_PROJQ) {
        arow = (size_t)blockIdx.y << 7; brow = n0; orow = arow;
        Ah = g_Xhi; Al = g_Xlo; lda = EE; Bh = g_Wqh; Bl = g_Wql; ldb = EE;
        oHi = g_Qhi; oLo = g_Qlo; ldo = EE; addb = true;
    } else if (mode == MODE_PROJK) {
        b = blockIdx.y >> 4;
        int tloc = (blockIdx.y & 15) << 7;
        first = seq_first(seq, b);
        if (tloc >= first) return;
        arow = (size_t)b * SS + tloc; brow = n0; orow = (size_t)b * JMAX + tloc;
        Ah = g_Xhi; Al = g_Xlo; lda = EE; Bh = g_Wkh; Bl = g_Wkl; ldb = EE;
        oHi = g_Khi; oLo = g_Klo; ldo = EE; addb = true;
    } else if (mode == MODE_SCORE) {
        b = blockIdx.z; first = seq_first(seq, b);
        if (n0 >= first) return;
        arow = (size_t)b * SS + ((size_t)blockIdx.y << 7);
        brow = (size_t)b * JMAX + n0;
        Ah = g_Qhi; Al = g_Qlo; lda = EE; Bh = g_Khi; Bl = g_Klo; ldb = EE;
        outF = g_P; ldo = JMAX; orow = arow; scale = INV_SQRT_DK;
    } else { // MODE_PV
        b = blockIdx.z; first = seq_first(seq, b);
        Kdim = (first + 63) & ~63;
        arow = (size_t)b * SS + ((size_t)blockIdx.y << 7);
        brow = (size_t)b * EE + n0;
        Ah = g_Phi; Al = g_Plo; lda = JMAX; Bh = g_Vth; Bl = g_Vtl; ldb = JMAX;
        outF = Hout; ldo = EE; orow = arow;
    }

    extern __shared__ char smem[];
    const uint32_t sbase = smem_to_u32(smem);
    const int tid  = threadIdx.x;
    const int lane = tid & 31, wid = tid >> 5;
    const int wm = wid >> 1, wn = wid & 1;          // 2 x 2 warp grid, warp tile 64x64

    const char* gsrc[4] = { (const char*)(Ah + arow * lda), (const char*)(Al + arow * lda),
                            (const char*)(Bh + brow * ldb), (const char*)(Bl + brow * ldb) };
    const size_t ldby[4] = { (size_t)lda * 2, (size_t)lda * 2,
                             (size_t)ldb * 2, (size_t)ldb * 2 };

    auto load_stage = [&](int s, int ki) {
        const size_t k0b = (size_t)ki * 64;          // 32 bf16 = 64 bytes
        const uint32_t sb = sbase + s * STAGE_SM;
        #pragma unroll
        for (int j = 0; j < 16; j++) {
            int t = tid + j * 128;                   // 2048 chunks of 16B
            int tile = t >> 9, row = (t >> 2) & 127, c = t & 3;
            uint32_t sa = sb + tile * TILE_SM + row * TSTRIDE + c * 16;
            const char* ga = gsrc[tile] + (size_t)row * ldby[tile] + k0b + c * 16;
            CP_ASYNC16(sa, ga);
        }
    };

    float acc[4][8][4];
    #pragma unroll
    for (int mt = 0; mt < 4; mt++)
        #pragma unroll
        for (int nt = 0; nt < 8; nt++)
            #pragma unroll
            for (int r = 0; r < 4; r++) acc[mt][nt][r] = 0.f;

    const int kt = Kdim >> 5;                        // BK = 32

    load_stage(0, 0);
    CP_COMMIT();

    for (int i = 0; i < kt; i++) {
        const int cur = i & 1;
        if (i + 1 < kt) { load_stage(cur ^ 1, i + 1); CP_COMMIT(); CP_WAIT(1); }
        else            { CP_WAIT(0); }
        __syncthreads();

        const uint32_t sb = sbase + cur * STAGE_SM;
        #pragma unroll
        for (int ks = 0; ks < 2; ks++) {             // two k16 halves of BK=32
            uint32_t ah[4][4], alr[4][4];
            #pragma unroll
            for (int mt = 0; mt < 4; mt++) {
                uint32_t ra = sb + (wm * 64 + mt * 16 + (lane & 15)) * TSTRIDE
                            + ks * 32 + ((lane >> 4) << 4);
                ldsm4(ah[mt],  ra);
                ldsm4(alr[mt], ra + TILE_SM);
            }
            uint32_t bh4[4][4], bl4[4][4];
            #pragma unroll
            for (int nt2 = 0; nt2 < 4; nt2++) {
                uint32_t rb = sb + 2 * TILE_SM
                            + (wn * 64 + nt2 * 16 + ((lane & 7) + ((lane >> 4) << 3))) * TSTRIDE
                            + ks * 32 + (((lane >> 3) & 1) << 4);
                ldsm4(bh4[nt2], rb);
                ldsm4(bl4[nt2], rb + TILE_SM);
            }
            #pragma unroll
            for (int p = 0; p < 3; p++) {
                #pragma unroll
                for (int mt = 0; mt < 4; mt++)
                    #pragma unroll
                    for (int nt2 = 0; nt2 < 4; nt2++)
                        #pragma unroll
                        for (int nn = 0; nn < 2; nn++) {
                            float* c = acc[mt][nt2 * 2 + nn];
                            const uint32_t* a = (p == 2) ? alr[mt] : ah[mt];
                            const uint32_t* bb = (p == 1) ? bl4[nt2] : bh4[nt2];
                            mma_bf16(c, a, bb[2 * nn], bb[2 * nn + 1]);
                        }
            }
        }
        __syncthreads();
    }

    // epilogue
    const int grp = lane >> 2, tig = lane & 3;
    #pragma unroll
    for (int mt = 0; mt < 4; mt++) {
        #pragma unroll
        for (int half = 0; half < 2; half++) {
            const size_t row = orow + wm * 64 + mt * 16 + grp + half * 8;
            float rsc = scale;
            if (mode == MODE_PV) rsc = g_invl[row];
            float vmax = __int_as_float(0xff800000);     // -inf (SCORE row max)
            #pragma unroll
            for (int nt = 0; nt < 8; nt++) {
                const int col = n0 + wn * 64 + nt * 8 + tig * 2;
                float v0 = acc[mt][nt][half * 2 + 0];
                float v1 = acc[mt][nt][half * 2 + 1];
                if (outF) {
                    float s0 = v0 * rsc, s1 = v1 * rsc;
                    *(float2*)&outF[row * ldo + col] = make_float2(s0, s1);
                    if (mode == MODE_SCORE) {
                        if (col < first)     vmax = fmaxf(vmax, s0);
                        if (col + 1 < first) vmax = fmaxf(vmax, s1);
                    }
                } else {
                    if (addb) { v0 += bias[col]; v1 += bias[col + 1]; }
                    __nv_bfloat16 h0, l0, h1, l1;
                    split2(v0, h0, l0); split2(v1, h1, l1);
                    *(uint32_t*)&oHi[row * ldo + col] = packbf(h0, h1);
                    *(uint32_t*)&oLo[row * ldo + col] = packbf(l0, l1);
                }
            }
            if (mode == MODE_SCORE) {
                // quad-reduce across tig (lanes 4*grp..4*grp+3 share the row)
                vmax = fmaxf(vmax, __shfl_xor_sync(0xffffffff, vmax, 1));
                vmax = fmaxf(vmax, __shfl_xor_sync(0xffffffff, vmax, 2));
                if (tig == 0 && vmax > -1e38f)
                    atomicMax(&g_rowmax[row], fenc(vmax));
            }
        }
    }
}

// ---------------- kernel: V projection (SIMT fp32), transposed split output --
__global__ __launch_bounds__(256) void v_gemm(
    const float* __restrict__ X, const float* __restrict__ W,
    const float* __restrict__ bias, const int* __restrict__ seq)
{
    const int tid = threadIdx.x;
    const int tx = tid & 15;
    const int ty = tid >> 4;

    const int b    = blockIdx.y >> 4;
    const int tloc = (blockIdx.y & 15) << 7;
    const int col0 = blockIdx.x << 7;
    const int first = seq_first(seq, b);
    if (tloc >= first) return;

    const int xrow0 = b * SS + tloc;

    __shared__ float As[16][128];
    __shared__ float Bs[16][128];

    float acc[8][8];
    #pragma unroll
    for (int i = 0; i < 8; i++)
        #pragma unroll
        for (int j = 0; j < 8; j++) acc[i][j] = 0.f;

    for (int k0 = 0; k0 < EE; k0 += 16) {
        #pragma unroll
        for (int v = tid; v < 512; v += 256) {
            int r = v >> 2;
            int c = (v & 3) << 2;
            float4 a = *(const float4*)&X[(size_t)(xrow0 + r) * EE + k0 + c];
            As[c + 0][r] = a.x; As[c + 1][r] = a.y;
            As[c + 2][r] = a.z; As[c + 3][r] = a.w;
            float4 wv = *(const float4*)&W[(size_t)(col0 + r) * EE + k0 + c];
            Bs[c + 0][r] = wv.x; Bs[c + 1][r] = wv.y;
            Bs[c + 2][r] = wv.z; Bs[c + 3][r] = wv.w;
        }
        __syncthreads();

        #pragma unroll
        for (int kk = 0; kk < 16; kk++) {
            float4 a0 = *(const float4*)&As[kk][ty * 8];
            float4 a1 = *(const float4*)&As[kk][ty * 8 + 4];
            float4 b0 = *(const float4*)&Bs[kk][tx * 8];
            float4 b1 = *(const float4*)&Bs[kk][tx * 8 + 4];
            float av[8] = {a0.x, a0.y, a0.z, a0.w, a1.x, a1.y, a1.z, a1.w};
            float bv[8] = {b0.x, b0.y, b0.z, b0.w, b1.x, b1.y, b1.z, b1.w};
            #pragma unroll
            for (int i = 0; i < 8; i++)
                #pragma unroll
                for (int j = 0; j < 8; j++)
                    acc[i][j] = fmaf(av[i], bv[j], acc[i][j]);
        }
        __syncthreads();
    }

    const int tok0 = tloc + ty * 8;
    #pragma unroll
    for (int j = 0; j < 8; j++) {
        const int e = col0 + tx * 8 + j;
        const float be = bias[e];
        uint32_t hu[4], lu[4];
        #pragma unroll
        for (int pr = 0; pr < 4; pr++) {
            __nv_bfloat16 h0, l0, h1, l1;
            split2(acc[pr * 2 + 0][j] + be, h0, l0);
            split2(acc[pr * 2 + 1][j] + be, h1, l1);
            hu[pr] = packbf(h0, h1);
            lu[pr] = packbf(l0, l1);
        }
        const size_t off = ((size_t)b * EE + e) * JMAX + tok0;
        *(uint4*)&g_Vth[off] = make_uint4(hu[0], hu[1], hu[2], hu[3]);
        *(uint4*)&g_Vtl[off] = make_uint4(lu[0], lu[1], lu[2], lu[3]);
    }
}

// ---------------- kernel: single-pass softmax (uses fused row max) -----------
__global__ __launch_bounds__(256) void softmax_rows(const int* __restrict__ seq)
{
    const int b = blockIdx.x >> 12;
    const int q = blockIdx.x & 4095;
    const int first = seq_first(seq, b);
    const float* row = g_P + ((size_t)b * SS + q) * JMAX;
    const int tid = threadIdx.x;

    __shared__ float red[256];

    const float m = fdec(g_rowmax[b * SS + q]);

    const int kpad = (first + 63) & ~63;
    const size_t ro = ((size_t)b * SS + q) * JMAX;
    float l = 0.f;
    for (int j = tid; j < kpad; j += 256) {
        float p = 0.f;
        if (j >= 1 && j < first) { p = __expf(row[j] - m); l += p; }
        __nv_bfloat16 h, lo;
        split2(p, h, lo);
        g_Phi[ro + j] = h;
        g_Plo[ro + j] = lo;
    }
    red[tid] = l;
    __syncthreads();
    #pragma unroll
    for (int s = 128; s > 0; s >>= 1) {
        if (tid < s) red[tid] += red[tid + s];
        __syncthreads();
    }
    if (tid == 0) g_invl[b * SS + q] = 1.0f / fmaxf(red[0], 1e-30f);
}

// ---------------------------------------------------------------------------
extern "C" void kernel_launch(void* const* d_in, const int* in_sizes, int n_in,
                              void* d_out, int out_size)
{
    const float* ebd = (const float*)d_in[0];
    const int*   seq = (const int*)d_in[1];
    const float* Wq = (const float*)d_in[2];
    const float* bq = (const float*)d_in[3];
    const float* Wk = (const float*)d_in[4];
    const float* bk = (const float*)d_in[5];
    const float* Wv = (const float*)d_in[6];
    const float* bv = (const float*)d_in[7];
    float* H = (float*)d_out;

    static cudaStream_t s2 = nullptr;
    static cudaEvent_t evFork = nullptr, evSplit = nullptr, evJoin = nullptr;
    static void* rowmax_ptr = nullptr;
    if (!s2) {
        cudaFuncSetAttribute(tc_gemm, cudaFuncAttributeMaxDynamicSharedMemorySize, SMEM_TC);
        cudaStreamCreateWithFlags(&s2, cudaStreamNonBlocking);
        cudaEventCreateWithFlags(&evFork, cudaEventDisableTiming);
        cudaEventCreateWithFlags(&evSplit, cudaEventDisableTiming);
        cudaEventCreateWithFlags(&evJoin, cudaEventDisableTiming);
        cudaGetSymbolAddress(&rowmax_ptr, g_rowmax);
    }

    // reset fused row-max accumulators (graph-legal memset node)
    cudaMemsetAsync(rowmax_ptr, 0, (size_t)BB * SS * sizeof(unsigned int), 0);

    // fork: v_gemm (no deps) on side stream
    cudaEventRecord(evFork, 0);
    cudaStreamWaitEvent(s2, evFork, 0);
    v_gemm<<<dim3(EE / 128, BB * (JMAX / 128)), 256, 0, s2>>>(ebd, Wv, bv, seq);

    // 0) fp32 -> split bf16 for X, Wq, Wk (main stream)
    {
        size_t n4 = NX / 4;
        split_sel<<<(unsigned)((n4 + 255) / 256), 256>>>(ebd, 0, n4);
        size_t w4 = (size_t)EE * EE / 4;
        split_sel<<<(unsigned)((w4 + 255) / 256), 256>>>(Wq, 1, w4);
        split_sel<<<(unsigned)((w4 + 255) / 256), 256>>>(Wk, 2, w4);
    }
    cudaEventRecord(evSplit, 0);

    // PROJK on side stream (after splits), PROJQ on main — overlap
    cudaStreamWaitEvent(s2, evSplit, 0);
    tc_gemm<<<dim3(EE / 128, BB * (JMAX / 128), 1), 128, SMEM_TC, s2>>>(MODE_PROJK, seq, bk, nullptr);
    cudaEventRecord(evJoin, s2);

    tc_gemm<<<dim3(EE / 128, BB * SS / 128, 1), 128, SMEM_TC>>>(MODE_PROJQ, seq, bq, nullptr);

    // join: SCORE needs K (and PV later needs V, ordered before PROJK on s2)
    cudaStreamWaitEvent(0, evJoin, 0);

    // 2) scores (fp32 out) + fused row max
    tc_gemm<<<dim3(JMAX / 128, SS / 128, BB), 128, SMEM_TC>>>(MODE_SCORE, seq, nullptr, nullptr);

    // 3) single-pass softmax -> unnormalized split exp + inv_l
    softmax_rows<<<BB * SS, 256>>>(seq);

    // 4) H = (P @ V) * inv_l
    tc_gemm<<<dim3(EE / 128, SS / 128, BB), 128, SMEM_TC>>>(MODE_PV, seq, nullptr, H);
}

// round 11
// speedup vs baseline: 1.0697x; 1.0156x over previous
#include <cuda_runtime.h>
#include <cuda_bf16.h>
#include <cstdint>

#define BB 8
#define SS 4096
#define EE 768
#define JMAX 2048
#define INV_SQRT_DK 0.03608439182435161f

#define NX ((size_t)BB * SS * EE)     // 25.2M
#define NK ((size_t)BB * JMAX * EE)   // 12.6M
#define NP ((size_t)BB * SS * JMAX)   // 67.1M

// ---------------- scratch (device globals; no allocations allowed) ----------
__device__ __nv_bfloat16 g_Xhi[NX], g_Xlo[NX];
__device__ __nv_bfloat16 g_Wqh[EE * EE], g_Wql[EE * EE];
__device__ __nv_bfloat16 g_Wkh[EE * EE], g_Wkl[EE * EE];
__device__ __nv_bfloat16 g_Qhi[NX], g_Qlo[NX];
__device__ __nv_bfloat16 g_Khi[NK], g_Klo[NK];
__device__ __nv_bfloat16 g_Vth[NK], g_Vtl[NK];   // [b][e][token] transposed V splits
__device__ float g_P[NP];
__device__ __nv_bfloat16 g_Phi[NP], g_Plo[NP];   // unnormalized exp splits
__device__ float g_invl[BB * SS];                 // per-row 1/sum
__device__ unsigned int g_rowmax[BB * SS];        // encoded per-row max (memset 0)

// ---------------- helpers ----------------------------------------------------
__device__ __forceinline__ uint32_t smem_to_u32(const void* p) {
    uint32_t a;
    asm("{ .reg .u64 t; cvta.to.shared.u64 t, %1; cvt.u32.u64 %0, t; }" : "=r"(a) : "l"(p));
    return a;
}
__device__ __forceinline__ int seq_first(const int* __restrict__ s, int b) {
    const bool is64 = (s[1] == 0);
    int v = is64 ? s[4 * b] : s[2 * b];
    if (v < 1) v = 1;
    if (v > JMAX) v = JMAX;
    return v;
}
__device__ __forceinline__ void split2(float v, __nv_bfloat16& h, __nv_bfloat16& l) {
    h = __float2bfloat16(v);
    l = __float2bfloat16(v - __bfloat162float(h));
}
__device__ __forceinline__ uint32_t packbf(__nv_bfloat16 a, __nv_bfloat16 b) {
    return (uint32_t)__bfloat16_as_ushort(a) | ((uint32_t)__bfloat16_as_ushort(b) << 16);
}
// order-preserving float<->uint encode (for atomicMax); 0 == "nothing yet"
__device__ __forceinline__ uint32_t fenc(float f) {
    int s = __float_as_int(f);
    return (uint32_t)(s ^ ((s >> 31) | 0x80000000));
}
__device__ __forceinline__ float fdec(uint32_t u) {
    int s = (u & 0x80000000u) ? (int)(u ^ 0x80000000u) : ~(int)u;
    return __int_as_float(s);
}

__device__ __forceinline__ void ldsm4(uint32_t* d, uint32_t a) {
    asm volatile("ldmatrix.sync.aligned.m8n8.x4.shared.b16 {%0,%1,%2,%3}, [%4];"
                 : "=r"(d[0]), "=r"(d[1]), "=r"(d[2]), "=r"(d[3]) : "r"(a));
}
__device__ __forceinline__ void mma_bf16(float* c, const uint32_t* a, uint32_t b0, uint32_t b1) {
    asm volatile(
        "mma.sync.aligned.m16n8k16.row.col.f32.bf16.bf16.f32 "
        "{%0,%1,%2,%3}, {%4,%5,%6,%7}, {%8,%9}, {%0,%1,%2,%3};"
        : "+f"(c[0]), "+f"(c[1]), "+f"(c[2]), "+f"(c[3])
        : "r"(a[0]), "r"(a[1]), "r"(a[2]), "r"(a[3]), "r"(b0), "r"(b1));
}
#define CP_ASYNC16(sa, ga) \
    asm volatile("cp.async.cg.shared.global [%0], [%1], 16;" :: "r"(sa), "l"(ga) : "memory")
#define CP_COMMIT() asm volatile("cp.async.commit_group;" ::: "memory")
#define CP_WAIT(n)  asm volatile("cp.async.wait_group %0;" :: "n"(n) : "memory")

// ---------------- kernel: fp32 -> (hi, lo) bf16 splits ------------------------
__global__ __launch_bounds__(256) void split_sel(const float* __restrict__ src,
                                                 int sel, size_t n4)
{
    size_t i = (size_t)blockIdx.x * 256 + threadIdx.x;
    if (i >= n4) return;
    __nv_bfloat16 *dh, *dl;
    if (sel == 0)      { dh = g_Xhi; dl = g_Xlo; }
    else if (sel == 1) { dh = g_Wqh; dl = g_Wql; }
    else               { dh = g_Wkh; dl = g_Wkl; }
    float4 v = ((const float4*)src)[i];
    __nv_bfloat16 h0, l0, h1, l1, h2, l2, h3, l3;
    split2(v.x, h0, l0); split2(v.y, h1, l1);
    split2(v.z, h2, l2); split2(v.w, h3, l3);
    ((uint2*)dh)[i] = make_uint2(packbf(h0, h1), packbf(h2, h3));
    ((uint2*)dl)[i] = make_uint2(packbf(l0, l1), packbf(l2, l3));
}

// ---------------- generic split-bf16 NT GEMM on mma.sync ---------------------
#define TSTRIDE 80
#define TILE_SM (128 * TSTRIDE)          // 10240
#define STAGE_SM (4 * TILE_SM)           // 40960
#define SMEM_TC (2 * STAGE_SM)           // 81920

#define MODE_PROJQ 0
#define MODE_PROJK 1
#define MODE_SCORE 2
#define MODE_PV    3

__global__ __launch_bounds__(128, 2) void tc_gemm(int mode, const int* __restrict__ seq,
                                                  const float* __restrict__ bias,
                                                  float* __restrict__ Hout)
{
    const int n0 = blockIdx.x << 7;
    int b = 0, first = 0, Kdim = EE;
    size_t arow, brow, orow;
    int lda, ldb, ldo = EE;
    const __nv_bfloat16 *Ah, *Al, *Bh, *Bl;
    float* outF = nullptr;
    __nv_bfloat16 *oHi = nullptr, *oLo = nullptr;
    float scale = 1.f;
    bool addb = false;

    if (mode == MODE_PROJQ) {
        arow = (size_t)blockIdx.y << 7; brow = n0; orow = arow;
        Ah = g_Xhi; Al = g_Xlo; lda = EE; Bh = g_Wqh; Bl = g_Wql; ldb = EE;
        oHi = g_Qhi; oLo = g_Qlo; ldo = EE; addb = true;
    } else if (mode == MODE_PROJK) {
        b = blockIdx.y >> 4;
        int tloc = (blockIdx.y & 15) << 7;
        first = seq_first(seq, b);
        if (tloc >= first) return;
        arow = (size_t)b * SS + tloc; brow = n0; orow = (size_t)b * JMAX + tloc;
        Ah = g_Xhi; Al = g_Xlo; lda = EE; Bh = g_Wkh; Bl = g_Wkl; ldb = EE;
        oHi = g_Khi; oLo = g_Klo; ldo = EE; addb = true;
    } else if (mode == MODE_SCORE) {
        b = blockIdx.z; first = seq_first(seq, b);
        if (n0 >= first) return;
        arow = (size_t)b * SS + ((size_t)blockIdx.y << 7);
        brow = (size_t)b * JMAX + n0;
        Ah = g_Qhi; Al = g_Qlo; lda = EE; Bh = g_Khi; Bl = g_Klo; ldb = EE;
        outF = g_P; ldo = JMAX; orow = arow; scale = INV_SQRT_DK;
    } else { // MODE_PV
        b = blockIdx.z; first = seq_first(seq, b);
        Kdim = (first + 63) & ~63;
        arow = (size_t)b * SS + ((size_t)blockIdx.y << 7);
        brow = (size_t)b * EE + n0;
        Ah = g_Phi; Al = g_Plo; lda = JMAX; Bh = g_Vth; Bl = g_Vtl; ldb = JMAX;
        outF = Hout; ldo = EE; orow = arow;
    }

    extern __shared__ char smem[];
    const uint32_t sbase = smem_to_u32(smem);
    const int tid  = threadIdx.x;
    const int lane = tid & 31, wid = tid >> 5;
    const int wm = wid >> 1, wn = wid & 1;          // 2 x 2 warp grid, warp tile 64x64

    const char* gsrc[4] = { (const char*)(Ah + arow * lda), (const char*)(Al + arow * lda),
                            (const char*)(Bh + brow * ldb), (const char*)(Bl + brow * ldb) };
    const size_t ldby[4] = { (size_t)lda * 2, (size_t)lda * 2,
                             (size_t)ldb * 2, (size_t)ldb * 2 };

    auto load_stage = [&](int s, int ki) {
        const size_t k0b = (size_t)ki * 64;          // 32 bf16 = 64 bytes
        const uint32_t sb = sbase + s * STAGE_SM;
        #pragma unroll
        for (int j = 0; j < 16; j++) {
            int t = tid + j * 128;                   // 2048 chunks of 16B
            int tile = t >> 9, row = (t >> 2) & 127, c = t & 3;
            uint32_t sa = sb + tile * TILE_SM + row * TSTRIDE + c * 16;
            const char* ga = gsrc[tile] + (size_t)row * ldby[tile] + k0b + c * 16;
            CP_ASYNC16(sa, ga);
        }
    };

    float acc[4][8][4];
    #pragma unroll
    for (int mt = 0; mt < 4; mt++)
        #pragma unroll
        for (int nt = 0; nt < 8; nt++)
            #pragma unroll
            for (int r = 0; r < 4; r++) acc[mt][nt][r] = 0.f;

    const int kt = Kdim >> 5;                        // BK = 32

    load_stage(0, 0);
    CP_COMMIT();

    for (int i = 0; i < kt; i++) {
        const int cur = i & 1;
        if (i + 1 < kt) { load_stage(cur ^ 1, i + 1); CP_COMMIT(); CP_WAIT(1); }
        else            { CP_WAIT(0); }
        __syncthreads();

        const uint32_t sb = sbase + cur * STAGE_SM;
        #pragma unroll
        for (int ks = 0; ks < 2; ks++) {             // two k16 halves of BK=32
            uint32_t ah[4][4], alr[4][4];
            #pragma unroll
            for (int mt = 0; mt < 4; mt++) {
                uint32_t ra = sb + (wm * 64 + mt * 16 + (lane & 15)) * TSTRIDE
                            + ks * 32 + ((lane >> 4) << 4);
                ldsm4(ah[mt],  ra);
                ldsm4(alr[mt], ra + TILE_SM);
            }
            uint32_t bh4[4][4], bl4[4][4];
            #pragma unroll
            for (int nt2 = 0; nt2 < 4; nt2++) {
                uint32_t rb = sb + 2 * TILE_SM
                            + (wn * 64 + nt2 * 16 + ((lane & 7) + ((lane >> 4) << 3))) * TSTRIDE
                            + ks * 32 + (((lane >> 3) & 1) << 4);
                ldsm4(bh4[nt2], rb);
                ldsm4(bl4[nt2], rb + TILE_SM);
            }
            #pragma unroll
            for (int p = 0; p < 3; p++) {
                #pragma unroll
                for (int mt = 0; mt < 4; mt++)
                    #pragma unroll
                    for (int nt2 = 0; nt2 < 4; nt2++)
                        #pragma unroll
                        for (int nn = 0; nn < 2; nn++) {
                            float* c = acc[mt][nt2 * 2 + nn];
                            const uint32_t* a = (p == 2) ? alr[mt] : ah[mt];
                            const uint32_t* bb = (p == 1) ? bl4[nt2] : bh4[nt2];
                            mma_bf16(c, a, bb[2 * nn], bb[2 * nn + 1]);
                        }
            }
        }
        __syncthreads();
    }

    // epilogue
    const int grp = lane >> 2, tig = lane & 3;
    #pragma unroll
    for (int mt = 0; mt < 4; mt++) {
        #pragma unroll
        for (int half = 0; half < 2; half++) {
            const size_t row = orow + wm * 64 + mt * 16 + grp + half * 8;
            float rsc = scale;
            if (mode == MODE_PV) rsc = g_invl[row];
            float vmax = __int_as_float(0xff800000);     // -inf (SCORE row max)
            #pragma unroll
            for (int nt = 0; nt < 8; nt++) {
                const int col = n0 + wn * 64 + nt * 8 + tig * 2;
                float v0 = acc[mt][nt][half * 2 + 0];
                float v1 = acc[mt][nt][half * 2 + 1];
                if (outF) {
                    float s0 = v0 * rsc, s1 = v1 * rsc;
                    *(float2*)&outF[row * ldo + col] = make_float2(s0, s1);
                    if (mode == MODE_SCORE) {
                        if (col < first)     vmax = fmaxf(vmax, s0);
                        if (col + 1 < first) vmax = fmaxf(vmax, s1);
                    }
                } else {
                    if (addb) { v0 += bias[col]; v1 += bias[col + 1]; }
                    __nv_bfloat16 h0, l0, h1, l1;
                    split2(v0, h0, l0); split2(v1, h1, l1);
                    *(uint32_t*)&oHi[row * ldo + col] = packbf(h0, h1);
                    *(uint32_t*)&oLo[row * ldo + col] = packbf(l0, l1);
                }
            }
            if (mode == MODE_SCORE) {
                // quad-reduce across tig (lanes 4*grp..4*grp+3 share the row)
                vmax = fmaxf(vmax, __shfl_xor_sync(0xffffffff, vmax, 1));
                vmax = fmaxf(vmax, __shfl_xor_sync(0xffffffff, vmax, 2));
                if (tig == 0 && vmax > -1e38f)
                    atomicMax(&g_rowmax[row], fenc(vmax));
            }
        }
    }
}

// ---------------- kernel: V projection (SIMT fp32), transposed split output --
__global__ __launch_bounds__(256) void v_gemm(
    const float* __restrict__ X, const float* __restrict__ W,
    const float* __restrict__ bias, const int* __restrict__ seq)
{
    const int tid = threadIdx.x;
    const int tx = tid & 15;
    const int ty = tid >> 4;

    const int b    = blockIdx.y >> 4;
    const int tloc = (blockIdx.y & 15) << 7;
    const int col0 = blockIdx.x << 7;
    const int first = seq_first(seq, b);
    if (tloc >= first) return;

    const int xrow0 = b * SS + tloc;

    __shared__ float As[16][128];
    __shared__ float Bs[16][128];

    float acc[8][8];
    #pragma unroll
    for (int i = 0; i < 8; i++)
        #pragma unroll
        for (int j = 0; j < 8; j++) acc[i][j] = 0.f;

    for (int k0 = 0; k0 < EE; k0 += 16) {
        #pragma unroll
        for (int v = tid; v < 512; v += 256) {
            int r = v >> 2;
            int c = (v & 3) << 2;
            float4 a = *(const float4*)&X[(size_t)(xrow0 + r) * EE + k0 + c];
            As[c + 0][r] = a.x; As[c + 1][r] = a.y;
            As[c + 2][r] = a.z; As[c + 3][r] = a.w;
            float4 wv = *(const float4*)&W[(size_t)(col0 + r) * EE + k0 + c];
            Bs[c + 0][r] = wv.x; Bs[c + 1][r] = wv.y;
            Bs[c + 2][r] = wv.z; Bs[c + 3][r] = wv.w;
        }
        __syncthreads();

        #pragma unroll
        for (int kk = 0; kk < 16; kk++) {
            float4 a0 = *(const float4*)&As[kk][ty * 8];
            float4 a1 = *(const float4*)&As[kk][ty * 8 + 4];
            float4 b0 = *(const float4*)&Bs[kk][tx * 8];
            float4 b1 = *(const float4*)&Bs[kk][tx * 8 + 4];
            float av[8] = {a0.x, a0.y, a0.z, a0.w, a1.x, a1.y, a1.z, a1.w};
            float bv[8] = {b0.x, b0.y, b0.z, b0.w, b1.x, b1.y, b1.z, b1.w};
            #pragma unroll
            for (int i = 0; i < 8; i++)
                #pragma unroll
                for (int j = 0; j < 8; j++)
                    acc[i][j] = fmaf(av[i], bv[j], acc[i][j]);
        }
        __syncthreads();
    }

    const int tok0 = tloc + ty * 8;
    #pragma unroll
    for (int j = 0; j < 8; j++) {
        const int e = col0 + tx * 8 + j;
        const float be = bias[e];
        uint32_t hu[4], lu[4];
        #pragma unroll
        for (int pr = 0; pr < 4; pr++) {
            __nv_bfloat16 h0, l0, h1, l1;
            split2(acc[pr * 2 + 0][j] + be, h0, l0);
            split2(acc[pr * 2 + 1][j] + be, h1, l1);
            hu[pr] = packbf(h0, h1);
            lu[pr] = packbf(l0, l1);
        }
        const size_t off = ((size_t)b * EE + e) * JMAX + tok0;
        *(uint4*)&g_Vth[off] = make_uint4(hu[0], hu[1], hu[2], hu[3]);
        *(uint4*)&g_Vtl[off] = make_uint4(lu[0], lu[1], lu[2], lu[3]);
    }
}

// ---------------- kernel: single-pass VECTORIZED softmax ---------------------
__global__ __launch_bounds__(256) void softmax_rows(const int* __restrict__ seq)
{
    const int b = blockIdx.x >> 12;
    const int q = blockIdx.x & 4095;
    const int first = seq_first(seq, b);
    const size_t ro = ((size_t)b * SS + q) * JMAX;
    const float4* row4 = (const float4*)(g_P + ro);
    uint2* phi2 = (uint2*)(g_Phi + ro);
    uint2* plo2 = (uint2*)(g_Plo + ro);
    const int tid = threadIdx.x;

    __shared__ float red[256];

    const float m = fdec(g_rowmax[b * SS + q]);

    const int kpad4 = ((first + 63) & ~63) >> 2;   // float4 count (multiple of 16)
    float l = 0.f;
    for (int j4 = tid; j4 < kpad4; j4 += 256) {
        const int j = j4 << 2;
        float4 v = row4[j4];
        float p0 = 0.f, p1 = 0.f, p2 = 0.f, p3 = 0.f;
        if (j + 0 >= 1 && j + 0 < first) { p0 = __expf(v.x - m); l += p0; }
        if (j + 1 < first)               { p1 = __expf(v.y - m); l += p1; }
        if (j + 2 < first)               { p2 = __expf(v.z - m); l += p2; }
        if (j + 3 < first)               { p3 = __expf(v.w - m); l += p3; }
        __nv_bfloat16 h0, l0, h1, l1, h2, l2, h3, l3;
        split2(p0, h0, l0); split2(p1, h1, l1);
        split2(p2, h2, l2); split2(p3, h3, l3);
        phi2[j4] = make_uint2(packbf(h0, h1), packbf(h2, h3));
        plo2[j4] = make_uint2(packbf(l0, l1), packbf(l2, l3));
    }
    red[tid] = l;
    __syncthreads();
    #pragma unroll
    for (int s = 128; s > 0; s >>= 1) {
        if (tid < s) red[tid] += red[tid + s];
        __syncthreads();
    }
    if (tid == 0) g_invl[b * SS + q] = 1.0f / fmaxf(red[0], 1e-30f);
}

// ---------------------------------------------------------------------------
extern "C" void kernel_launch(void* const* d_in, const int* in_sizes, int n_in,
                              void* d_out, int out_size)
{
    const float* ebd = (const float*)d_in[0];
    const int*   seq = (const int*)d_in[1];
    const float* Wq = (const float*)d_in[2];
    const float* bq = (const float*)d_in[3];
    const float* Wk = (const float*)d_in[4];
    const float* bk = (const float*)d_in[5];
    const float* Wv = (const float*)d_in[6];
    const float* bv = (const float*)d_in[7];
    float* H = (float*)d_out;

    static cudaStream_t s2 = nullptr;
    static cudaEvent_t evFork = nullptr, evSplit = nullptr, evJoin = nullptr;
    static void* rowmax_ptr = nullptr;
    if (!s2) {
        cudaFuncSetAttribute(tc_gemm, cudaFuncAttributeMaxDynamicSharedMemorySize, SMEM_TC);
        cudaStreamCreateWithFlags(&s2, cudaStreamNonBlocking);
        cudaEventCreateWithFlags(&evFork, cudaEventDisableTiming);
        cudaEventCreateWithFlags(&evSplit, cudaEventDisableTiming);
        cudaEventCreateWithFlags(&evJoin, cudaEventDisableTiming);
        cudaGetSymbolAddress(&rowmax_ptr, g_rowmax);
    }

    // reset fused row-max accumulators (graph-legal memset node)
    cudaMemsetAsync(rowmax_ptr, 0, (size_t)BB * SS * sizeof(unsigned int), 0);

    // fork: v_gemm (no deps) on side stream
    cudaEventRecord(evFork, 0);
    cudaStreamWaitEvent(s2, evFork, 0);
    v_gemm<<<dim3(EE / 128, BB * (JMAX / 128)), 256, 0, s2>>>(ebd, Wv, bv, seq);

    // 0) fp32 -> split bf16 for X, Wq, Wk (main stream)
    {
        size_t n4 = NX / 4;
        split_sel<<<(unsigned)((n4 + 255) / 256), 256>>>(ebd, 0, n4);
        size_t w4 = (size_t)EE * EE / 4;
        split_sel<<<(unsigned)((w4 + 255) / 256), 256>>>(Wq, 1, w4);
        split_sel<<<(unsigned)((w4 + 255) / 256), 256>>>(Wk, 2, w4);
    }
    cudaEventRecord(evSplit, 0);

    // PROJK on side stream (after splits), PROJQ on main — overlap
    cudaStreamWaitEvent(s2, evSplit, 0);
    tc_gemm<<<dim3(EE / 128, BB * (JMAX / 128), 1), 128, SMEM_TC, s2>>>(MODE_PROJK, seq, bk, nullptr);
    cudaEventRecord(evJoin, s2);

    tc_gemm<<<dim3(EE / 128, BB * SS / 128, 1), 128, SMEM_TC>>>(MODE_PROJQ, seq, bq, nullptr);

    // join: SCORE needs K (and PV later needs V, ordered before PROJK on s2)
    cudaStreamWaitEvent(0, evJoin, 0);

    // 2) scores (fp32 out) + fused row max
    tc_gemm<<<dim3(JMAX / 128, SS / 128, BB), 128, SMEM_TC>>>(MODE_SCORE, seq, nullptr, nullptr);

    // 3) single-pass vectorized softmax -> unnormalized split exp + inv_l
    softmax_rows<<<BB * SS, 256>>>(seq);

    // 4) H = (P @ V) * inv_l
    tc_gemm<<<dim3(EE / 128, SS / 128, BB), 128, SMEM_TC>>>(MODE_PV, seq, nullptr, H);
}

// round 12
// speedup vs baseline: 1.1109x; 1.0386x over previous
#include <cuda_runtime.h>
#include <cuda_bf16.h>
#include <cstdint>

#define BB 8
#define SS 4096
#define EE 768
#define JMAX 2048
#define INV_SQRT_DK 0.03608439182435161f

#define NX ((size_t)BB * SS * EE)     // 25.2M
#define NK ((size_t)BB * JMAX * EE)   // 12.6M
#define NP ((size_t)BB * SS * JMAX)   // 67.1M

// ---------------- scratch (device globals; no allocations allowed) ----------
__device__ __nv_bfloat16 g_Xhi[NX], g_Xlo[NX];
__device__ __nv_bfloat16 g_Wqh[EE * EE], g_Wql[EE * EE];
__device__ __nv_bfloat16 g_Wkh[EE * EE], g_Wkl[EE * EE];
__device__ __nv_bfloat16 g_Qhi[NX], g_Qlo[NX];
__device__ __nv_bfloat16 g_Khi[NK], g_Klo[NK];
__device__ __nv_bfloat16 g_Vth[NK], g_Vtl[NK];   // [b][e][token] transposed V splits
__device__ __nv_bfloat16 g_Phi[NP], g_Plo[NP];   // unnormalized exp splits
__device__ float g_partial[(size_t)BB * SS * 32]; // per-(row, ctile, wn) sums
__device__ float g_invl[BB * SS];                 // per-row 1/sum

// ---------------- helpers ----------------------------------------------------
__device__ __forceinline__ uint32_t smem_to_u32(const void* p) {
    uint32_t a;
    asm("{ .reg .u64 t; cvta.to.shared.u64 t, %1; cvt.u32.u64 %0, t; }" : "=r"(a) : "l"(p));
    return a;
}
__device__ __forceinline__ int seq_first(const int* __restrict__ s, int b) {
    const bool is64 = (s[1] == 0);
    int v = is64 ? s[4 * b] : s[2 * b];
    if (v < 1) v = 1;
    if (v > JMAX) v = JMAX;
    return v;
}
__device__ __forceinline__ void split2(float v, __nv_bfloat16& h, __nv_bfloat16& l) {
    h = __float2bfloat16(v);
    l = __float2bfloat16(v - __bfloat162float(h));
}
__device__ __forceinline__ uint32_t packbf(__nv_bfloat16 a, __nv_bfloat16 b) {
    return (uint32_t)__bfloat16_as_ushort(a) | ((uint32_t)__bfloat16_as_ushort(b) << 16);
}

__device__ __forceinline__ void ldsm4(uint32_t* d, uint32_t a) {
    asm volatile("ldmatrix.sync.aligned.m8n8.x4.shared.b16 {%0,%1,%2,%3}, [%4];"
                 : "=r"(d[0]), "=r"(d[1]), "=r"(d[2]), "=r"(d[3]) : "r"(a));
}
__device__ __forceinline__ void mma_bf16(float* c, const uint32_t* a, uint32_t b0, uint32_t b1) {
    asm volatile(
        "mma.sync.aligned.m16n8k16.row.col.f32.bf16.bf16.f32 "
        "{%0,%1,%2,%3}, {%4,%5,%6,%7}, {%8,%9}, {%0,%1,%2,%3};"
        : "+f"(c[0]), "+f"(c[1]), "+f"(c[2]), "+f"(c[3])
        : "r"(a[0]), "r"(a[1]), "r"(a[2]), "r"(a[3]), "r"(b0), "r"(b1));
}
#define CP_ASYNC16(sa, ga) \
    asm volatile("cp.async.cg.shared.global [%0], [%1], 16;" :: "r"(sa), "l"(ga) : "memory")
#define CP_COMMIT() asm volatile("cp.async.commit_group;" ::: "memory")
#define CP_WAIT(n)  asm volatile("cp.async.wait_group %0;" :: "n"(n) : "memory")

// ---------------- kernel: fp32 -> (hi, lo) bf16 splits ------------------------
__global__ __launch_bounds__(256) void split_sel(const float* __restrict__ src,
                                                 int sel, size_t n4)
{
    size_t i = (size_t)blockIdx.x * 256 + threadIdx.x;
    if (i >= n4) return;
    __nv_bfloat16 *dh, *dl;
    if (sel == 0)      { dh = g_Xhi; dl = g_Xlo; }
    else if (sel == 1) { dh = g_Wqh; dl = g_Wql; }
    else               { dh = g_Wkh; dl = g_Wkl; }
    float4 v = ((const float4*)src)[i];
    __nv_bfloat16 h0, l0, h1, l1, h2, l2, h3, l3;
    split2(v.x, h0, l0); split2(v.y, h1, l1);
    split2(v.z, h2, l2); split2(v.w, h3, l3);
    ((uint2*)dh)[i] = make_uint2(packbf(h0, h1), packbf(h2, h3));
    ((uint2*)dl)[i] = make_uint2(packbf(l0, l1), packbf(l2, l3));
}

// ---------------- generic split-bf16 NT GEMM on mma.sync ---------------------
#define TSTRIDE 80
#define TILE_SM (128 * TSTRIDE)          // 10240
#define STAGE_SM (4 * TILE_SM)           // 40960
#define SMEM_TC (2 * STAGE_SM)           // 81920

#define MODE_PROJQ 0
#define MODE_PROJK 1
#define MODE_SCORE 2
#define MODE_PV    3

__global__ __launch_bounds__(128, 2) void tc_gemm(int mode, const int* __restrict__ seq,
                                                  const float* __restrict__ bias,
                                                  float* __restrict__ Hout)
{
    const int n0 = blockIdx.x << 7;
    int b = 0, first = 0, Kdim = EE;
    size_t arow, brow, orow;
    int lda, ldb, ldo = EE;
    const __nv_bfloat16 *Ah, *Al, *Bh, *Bl;
    float* outF = nullptr;
    __nv_bfloat16 *oHi = nullptr, *oLo = nullptr;
    bool addb = false;

    if (mode == MODE_PROJQ) {
        arow = (size_t)blockIdx.y << 7; brow = n0; orow = arow;
        Ah = g_Xhi; Al = g_Xlo; lda = EE; Bh = g_Wqh; Bl = g_Wql; ldb = EE;
        oHi = g_Qhi; oLo = g_Qlo; ldo = EE; addb = true;
    } else if (mode == MODE_PROJK) {
        b = blockIdx.y >> 4;
        int tloc = (blockIdx.y & 15) << 7;
        first = seq_first(seq, b);
        if (tloc >= first) return;
        arow = (size_t)b * SS + tloc; brow = n0; orow = (size_t)b * JMAX + tloc;
        Ah = g_Xhi; Al = g_Xlo; lda = EE; Bh = g_Wkh; Bl = g_Wkl; ldb = EE;
        oHi = g_Khi; oLo = g_Klo; ldo = EE; addb = true;
    } else if (mode == MODE_SCORE) {
        b = blockIdx.z; first = seq_first(seq, b);
        if (n0 >= first) return;
        arow = (size_t)b * SS + ((size_t)blockIdx.y << 7);
        brow = (size_t)b * JMAX + n0;
        Ah = g_Qhi; Al = g_Qlo; lda = EE; Bh = g_Khi; Bl = g_Klo; ldb = EE;
        oHi = g_Phi; oLo = g_Plo; ldo = JMAX; orow = arow;
    } else { // MODE_PV
        b = blockIdx.z; first = seq_first(seq, b);
        Kdim = (first + 63) & ~63;
        arow = (size_t)b * SS + ((size_t)blockIdx.y << 7);
        brow = (size_t)b * EE + n0;
        Ah = g_Phi; Al = g_Plo; lda = JMAX; Bh = g_Vth; Bl = g_Vtl; ldb = JMAX;
        outF = Hout; ldo = EE; orow = arow;
    }

    extern __shared__ char smem[];
    const uint32_t sbase = smem_to_u32(smem);
    const int tid  = threadIdx.x;
    const int lane = tid & 31, wid = tid >> 5;
    const int wm = wid >> 1, wn = wid & 1;          // 2 x 2 warp grid, warp tile 64x64

    const char* gsrc[4] = { (const char*)(Ah + arow * lda), (const char*)(Al + arow * lda),
                            (const char*)(Bh + brow * ldb), (const char*)(Bl + brow * ldb) };
    const size_t ldby[4] = { (size_t)lda * 2, (size_t)lda * 2,
                             (size_t)ldb * 2, (size_t)ldb * 2 };

    auto load_stage = [&](int s, int ki) {
        const size_t k0b = (size_t)ki * 64;          // 32 bf16 = 64 bytes
        const uint32_t sb = sbase + s * STAGE_SM;
        #pragma unroll
        for (int j = 0; j < 16; j++) {
            int t = tid + j * 128;                   // 2048 chunks of 16B
            int tile = t >> 9, row = (t >> 2) & 127, c = t & 3;
            uint32_t sa = sb + tile * TILE_SM + row * TSTRIDE + c * 16;
            const char* ga = gsrc[tile] + (size_t)row * ldby[tile] + k0b + c * 16;
            CP_ASYNC16(sa, ga);
        }
    };

    float acc[4][8][4];
    #pragma unroll
    for (int mt = 0; mt < 4; mt++)
        #pragma unroll
        for (int nt = 0; nt < 8; nt++)
            #pragma unroll
            for (int r = 0; r < 4; r++) acc[mt][nt][r] = 0.f;

    const int kt = Kdim >> 5;                        // BK = 32

    load_stage(0, 0);
    CP_COMMIT();

    for (int i = 0; i < kt; i++) {
        const int cur = i & 1;
        if (i + 1 < kt) { load_stage(cur ^ 1, i + 1); CP_COMMIT(); CP_WAIT(1); }
        else            { CP_WAIT(0); }
        __syncthreads();

        const uint32_t sb = sbase + cur * STAGE_SM;
        #pragma unroll
        for (int ks = 0; ks < 2; ks++) {             // two k16 halves of BK=32
            uint32_t ah[4][4], alr[4][4];
            #pragma unroll
            for (int mt = 0; mt < 4; mt++) {
                uint32_t ra = sb + (wm * 64 + mt * 16 + (lane & 15)) * TSTRIDE
                            + ks * 32 + ((lane >> 4) << 4);
                ldsm4(ah[mt],  ra);
                ldsm4(alr[mt], ra + TILE_SM);
            }
            uint32_t bh4[4][4], bl4[4][4];
            #pragma unroll
            for (int nt2 = 0; nt2 < 4; nt2++) {
                uint32_t rb = sb + 2 * TILE_SM
                            + (wn * 64 + nt2 * 16 + ((lane & 7) + ((lane >> 4) << 3))) * TSTRIDE
                            + ks * 32 + (((lane >> 3) & 1) << 4);
                ldsm4(bh4[nt2], rb);
                ldsm4(bl4[nt2], rb + TILE_SM);
            }
            #pragma unroll
            for (int p = 0; p < 3; p++) {
                #pragma unroll
                for (int mt = 0; mt < 4; mt++)
                    #pragma unroll
                    for (int nt2 = 0; nt2 < 4; nt2++)
                        #pragma unroll
                        for (int nn = 0; nn < 2; nn++) {
                            float* c = acc[mt][nt2 * 2 + nn];
                            const uint32_t* a = (p == 2) ? alr[mt] : ah[mt];
                            const uint32_t* bb = (p == 1) ? bl4[nt2] : bh4[nt2];
                            mma_bf16(c, a, bb[2 * nn], bb[2 * nn + 1]);
                        }
            }
        }
        __syncthreads();
    }

    // epilogue
    const int grp = lane >> 2, tig = lane & 3;
    #pragma unroll
    for (int mt = 0; mt < 4; mt++) {
        #pragma unroll
        for (int half = 0; half < 2; half++) {
            const size_t row = orow + wm * 64 + mt * 16 + grp + half * 8;
            if (mode == MODE_SCORE) {
                // exp + split write + deterministic partial row sum
                float rsum = 0.f;
                #pragma unroll
                for (int nt = 0; nt < 8; nt++) {
                    const int col = n0 + wn * 64 + nt * 8 + tig * 2;
                    float p0 = 0.f, p1 = 0.f;
                    if (col >= 1 && col < first) {
                        p0 = __expf(acc[mt][nt][half * 2 + 0] * INV_SQRT_DK);
                        rsum += p0;
                    }
                    if (col + 1 >= 1 && col + 1 < first) {
                        p1 = __expf(acc[mt][nt][half * 2 + 1] * INV_SQRT_DK);
                        rsum += p1;
                    }
                    __nv_bfloat16 h0, l0, h1, l1;
                    split2(p0, h0, l0); split2(p1, h1, l1);
                    *(uint32_t*)&oHi[row * ldo + col] = packbf(h0, h1);
                    *(uint32_t*)&oLo[row * ldo + col] = packbf(l0, l1);
                }
                rsum += __shfl_xor_sync(0xffffffff, rsum, 1);
                rsum += __shfl_xor_sync(0xffffffff, rsum, 2);
                if (tig == 0)
                    g_partial[row * 32 + (size_t)blockIdx.x * 2 + wn] = rsum;
            } else if (outF) {   // PV
                const float rsc = g_invl[row];
                #pragma unroll
                for (int nt = 0; nt < 8; nt++) {
                    const int col = n0 + wn * 64 + nt * 8 + tig * 2;
                    *(float2*)&outF[row * ldo + col] =
                        make_float2(acc[mt][nt][half * 2 + 0] * rsc,
                                    acc[mt][nt][half * 2 + 1] * rsc);
                }
            } else {             // projections
                #pragma unroll
                for (int nt = 0; nt < 8; nt++) {
                    const int col = n0 + wn * 64 + nt * 8 + tig * 2;
                    float v0 = acc[mt][nt][half * 2 + 0];
                    float v1 = acc[mt][nt][half * 2 + 1];
                    if (addb) { v0 += bias[col]; v1 += bias[col + 1]; }
                    __nv_bfloat16 h0, l0, h1, l1;
                    split2(v0, h0, l0); split2(v1, h1, l1);
                    *(uint32_t*)&oHi[row * ldo + col] = packbf(h0, h1);
                    *(uint32_t*)&oLo[row * ldo + col] = packbf(l0, l1);
                }
            }
        }
    }
}

// ---------------- kernel: fold partial sums -> inv_l -------------------------
__global__ __launch_bounds__(256) void row_sums(const int* __restrict__ seq)
{
    const int row = blockIdx.x * 256 + threadIdx.x;
    if (row >= BB * SS) return;
    const int b = row >> 12;
    const int first = seq_first(seq, b);
    const int np = 2 * ((first + 127) >> 7);       // partials written for this row
    const float* p = &g_partial[(size_t)row * 32];
    float s = 0.f;
    for (int i = 0; i < np; i++) s += p[i];
    g_invl[row] = 1.0f / fmaxf(s, 1e-30f);
}

// ---------------- kernel: V projection (SIMT fp32), transposed split output --
__global__ __launch_bounds__(256) void v_gemm(
    const float* __restrict__ X, const float* __restrict__ W,
    const float* __restrict__ bias, const int* __restrict__ seq)
{
    const int tid = threadIdx.x;
    const int tx = tid & 15;
    const int ty = tid >> 4;

    const int b    = blockIdx.y >> 4;
    const int tloc = (blockIdx.y & 15) << 7;
    const int col0 = blockIdx.x << 7;
    const int first = seq_first(seq, b);
    if (tloc >= first) return;

    const int xrow0 = b * SS + tloc;

    __shared__ float As[16][128];
    __shared__ float Bs[16][128];

    float acc[8][8];
    #pragma unroll
    for (int i = 0; i < 8; i++)
        #pragma unroll
        for (int j = 0; j < 8; j++) acc[i][j] = 0.f;

    for (int k0 = 0; k0 < EE; k0 += 16) {
        #pragma unroll
        for (int v = tid; v < 512; v += 256) {
            int r = v >> 2;
            int c = (v & 3) << 2;
            float4 a = *(const float4*)&X[(size_t)(xrow0 + r) * EE + k0 + c];
            As[c + 0][r] = a.x; As[c + 1][r] = a.y;
            As[c + 2][r] = a.z; As[c + 3][r] = a.w;
            float4 wv = *(const float4*)&W[(size_t)(col0 + r) * EE + k0 + c];
            Bs[c + 0][r] = wv.x; Bs[c + 1][r] = wv.y;
            Bs[c + 2][r] = wv.z; Bs[c + 3][r] = wv.w;
        }
        __syncthreads();

        #pragma unroll
        for (int kk = 0; kk < 16; kk++) {
            float4 a0 = *(const float4*)&As[kk][ty * 8];
            float4 a1 = *(const float4*)&As[kk][ty * 8 + 4];
            float4 b0 = *(const float4*)&Bs[kk][tx * 8];
            float4 b1 = *(const float4*)&Bs[kk][tx * 8 + 4];
            float av[8] = {a0.x, a0.y, a0.z, a0.w, a1.x, a1.y, a1.z, a1.w};
            float bv[8] = {b0.x, b0.y, b0.z, b0.w, b1.x, b1.y, b1.z, b1.w};
            #pragma unroll
            for (int i = 0; i < 8; i++)
                #pragma unroll
                for (int j = 0; j < 8; j++)
                    acc[i][j] = fmaf(av[i], bv[j], acc[i][j]);
        }
        __syncthreads();
    }

    const int tok0 = tloc + ty * 8;
    #pragma unroll
    for (int j = 0; j < 8; j++) {
        const int e = col0 + tx * 8 + j;
        const float be = bias[e];
        uint32_t hu[4], lu[4];
        #pragma unroll
        for (int pr = 0; pr < 4; pr++) {
            __nv_bfloat16 h0, l0, h1, l1;
            split2(acc[pr * 2 + 0][j] + be, h0, l0);
            split2(acc[pr * 2 + 1][j] + be, h1, l1);
            hu[pr] = packbf(h0, h1);
            lu[pr] = packbf(l0, l1);
        }
        const size_t off = ((size_t)b * EE + e) * JMAX + tok0;
        *(uint4*)&g_Vth[off] = make_uint4(hu[0], hu[1], hu[2], hu[3]);
        *(uint4*)&g_Vtl[off] = make_uint4(lu[0], lu[1], lu[2], lu[3]);
    }
}

// ---------------------------------------------------------------------------
extern "C" void kernel_launch(void* const* d_in, const int* in_sizes, int n_in,
                              void* d_out, int out_size)
{
    const float* ebd = (const float*)d_in[0];
    const int*   seq = (const int*)d_in[1];
    const float* Wq = (const float*)d_in[2];
    const float* bq = (const float*)d_in[3];
    const float* Wk = (const float*)d_in[4];
    const float* bk = (const float*)d_in[5];
    const float* Wv = (const float*)d_in[6];
    const float* bv = (const float*)d_in[7];
    float* H = (float*)d_out;

    static cudaStream_t s2 = nullptr;
    static cudaEvent_t evFork = nullptr, evSplit = nullptr, evJoin = nullptr;
    if (!s2) {
        cudaFuncSetAttribute(tc_gemm, cudaFuncAttributeMaxDynamicSharedMemorySize, SMEM_TC);
        cudaStreamCreateWithFlags(&s2, cudaStreamNonBlocking);
        cudaEventCreateWithFlags(&evFork, cudaEventDisableTiming);
        cudaEventCreateWithFlags(&evSplit, cudaEventDisableTiming);
        cudaEventCreateWithFlags(&evJoin, cudaEventDisableTiming);
    }

    // fork: v_gemm (no deps) on side stream
    cudaEventRecord(evFork, 0);
    cudaStreamWaitEvent(s2, evFork, 0);
    v_gemm<<<dim3(EE / 128, BB * (JMAX / 128)), 256, 0, s2>>>(ebd, Wv, bv, seq);

    // 0) fp32 -> split bf16 for X, Wq, Wk (main stream)
    {
        size_t n4 = NX / 4;
        split_sel<<<(unsigned)((n4 + 255) / 256), 256>>>(ebd, 0, n4);
        size_t w4 = (size_t)EE * EE / 4;
        split_sel<<<(unsigned)((w4 + 255) / 256), 256>>>(Wq, 1, w4);
        split_sel<<<(unsigned)((w4 + 255) / 256), 256>>>(Wk, 2, w4);
    }
    cudaEventRecord(evSplit, 0);

    // PROJK on side stream (after splits), PROJQ on main — overlap
    cudaStreamWaitEvent(s2, evSplit, 0);
    tc_gemm<<<dim3(EE / 128, BB * (JMAX / 128), 1), 128, SMEM_TC, s2>>>(MODE_PROJK, seq, bk, nullptr);
    cudaEventRecord(evJoin, s2);

    tc_gemm<<<dim3(EE / 128, BB * SS / 128, 1), 128, SMEM_TC>>>(MODE_PROJQ, seq, bq, nullptr);

    // join: SCORE needs K (and PV later needs V, ordered before PROJK on s2)
    cudaStreamWaitEvent(0, evJoin, 0);

    // 2) scores -> exp splits + deterministic partial sums (no fp32 P!)
    tc_gemm<<<dim3(JMAX / 128, SS / 128, BB), 128, SMEM_TC>>>(MODE_SCORE, seq, nullptr, nullptr);

    // 3) fold partials -> inv_l
    row_sums<<<(BB * SS + 255) / 256, 256>>>(seq);

    // 4) H = (P @ V) * inv_l
    tc_gemm<<<dim3(EE / 128, SS / 128, BB), 128, SMEM_TC>>>(MODE_PV, seq, nullptr, H);
}